// round 8
// baseline (speedup 1.0000x reference)
#include <cuda_runtime.h>
#include <cuda_fp16.h>
#include <cstdint>

#define B_   1024
#define D_   1024
#define G_   4096
#define BAR_ 32
#define EPS_ 1e-5f

// GEMM tiling: CTA 128x256, BK=32, 512 threads (16 warps, each 64x32)
#define TM 128
#define TN 256
#define BK 32
#define NSTAGE 3
#define A_BYTES  (TM*BK*2)                // 8192 per array
#define B_BYTES  (TN*BK*2)                // 16384 per array
#define STG_BYTES (2*A_BYTES + 2*B_BYTES) // 49152
#define SMEM_BYTES (NSTAGE*STG_BYTES)     // 147456

// ---------------- device scratch ----------------
__device__ float g_sum[D_], g_sumsq[D_];
__device__ float g_x0[B_*G_];
__device__ float g_c0[B_*D_], g_c1[B_*D_];
__device__ float g_bi0[G_], g_bh0[G_], g_bi1[G_], g_bh1[G_];   // interleaved biases
__device__ __align__(128) __half g_znh[B_*D_],  g_znl[B_*D_];
__device__ __align__(128) __half g_h0h[2][B_*D_], g_h0l[2][B_*D_];
__device__ __align__(128) __half g_histh[(size_t)BAR_*B_*D_], g_histl[(size_t)BAR_*B_*D_];
__device__ __align__(128) __half g_wih0h[G_*D_], g_wih0l[G_*D_];
__device__ __align__(128) __half g_whh0h[G_*D_], g_whh0l[G_*D_];
__device__ __align__(128) __half g_wih1h[G_*D_], g_wih1l[G_*D_];
__device__ __align__(128) __half g_whh1h[G_*D_], g_whh1l[G_*D_];
__device__ __align__(128) __half g_wlinh[D_*D_], g_wlinl[D_*D_];

// ---------------- helpers ----------------
__device__ __forceinline__ uint32_t s2u(const void* p){
    uint32_t a;
    asm("{ .reg .u64 t; cvta.to.shared.u64 t, %1; cvt.u32.u64 %0, t; }" : "=r"(a) : "l"(p));
    return a;
}
__device__ __forceinline__ float sigf(float x){ return 1.f/(1.f+__expf(-x)); }

__device__ __forceinline__ void hsplit(float x, __half& hi, __half& lo){
    __half h = __float2half_rn(x);
    hi = h;
    lo = __float2half_rn(x - __half2float(h));
}

__device__ __forceinline__ void cp16(uint32_t dst, const void* src){
    asm volatile("cp.async.cg.shared.global [%0], [%1], 16;"
                 :: "r"(dst), "l"(__cvta_generic_to_global(src)));
}
#define CP_COMMIT() asm volatile("cp.async.commit_group;" ::: "memory")

__device__ __forceinline__ void mma16(float* c, const uint32_t* a, const uint32_t* b){
    asm volatile(
        "mma.sync.aligned.m16n8k16.row.col.f32.f16.f16.f32 "
        "{%0,%1,%2,%3}, {%4,%5,%6,%7}, {%8,%9}, {%0,%1,%2,%3};"
        : "+f"(c[0]), "+f"(c[1]), "+f"(c[2]), "+f"(c[3])
        : "r"(a[0]), "r"(a[1]), "r"(a[2]), "r"(a[3]), "r"(b[0]), "r"(b[1]));
}
__device__ __forceinline__ void ldsm4(uint32_t& r0, uint32_t& r1, uint32_t& r2,
                                      uint32_t& r3, uint32_t addr){
    asm volatile("ldmatrix.sync.aligned.m8n8.x4.shared.b16 {%0,%1,%2,%3}, [%4];"
                 : "=r"(r0), "=r"(r1), "=r"(r2), "=r"(r3) : "r"(addr));
}

// ---------------- BatchNorm ----------------
__global__ void bn_reduce(const float* __restrict__ z){
    int c = blockIdx.x, tid = threadIdx.x;
    float s = 0.f, s2 = 0.f;
    for (int r = tid; r < B_; r += 256){
        float v = z[(size_t)r*D_ + c]; s += v; s2 += v*v;
    }
    __shared__ float sh[256], sh2[256];
    sh[tid]=s; sh2[tid]=s2; __syncthreads();
    for (int o=128;o>0;o>>=1){
        if (tid<o){ sh[tid]+=sh[tid+o]; sh2[tid]+=sh2[tid+o]; }
        __syncthreads();
    }
    if (tid==0){ g_sum[c]=sh[0]; g_sumsq[c]=sh2[0]; }
}

__global__ void bn_apply(const float* __restrict__ z, const float* __restrict__ gamma,
                         const float* __restrict__ beta){
    int idx = blockIdx.x*256 + threadIdx.x;
    int d = idx & (D_-1);
    float mean = g_sum[d]*(1.f/B_);
    float var  = g_sumsq[d]*(1.f/B_) - mean*mean;
    float v = (z[idx]-mean)*rsqrtf(var+EPS_)*gamma[d] + beta[d];
    __half h, l; hsplit(v, h, l);
    g_znh[idx]=h;    g_znl[idx]=l;
    g_h0h[0][idx]=h; g_h0l[0][idx]=l;
    g_c0[idx]=v;     g_c1[idx]=v;
}

// ---------------- weight split fp32 -> fp16 hi/lo, gate-interleaved rows ----------------
// new row r' = dim*4 + gate  <-  old row gate*1024 + dim
__global__ void split_int(const float* __restrict__ W, __half* __restrict__ hi,
                          __half* __restrict__ lo){
    int i = blockIdx.x*256 + threadIdx.x;
    int col = i & (D_-1);
    int rp  = i >> 10;
    int gate = rp & 3, dim = rp >> 2;
    float v = W[((size_t)(gate<<10) + dim)*D_ + col];
    __half h, l; hsplit(v, h, l);
    hi[i]=h; lo[i]=l;
}
__global__ void split_plain(const float* __restrict__ W, __half* __restrict__ hi,
                            __half* __restrict__ lo, int n){
    int i = blockIdx.x*256 + threadIdx.x;
    if (i < n){ __half h, l; hsplit(W[i], h, l); hi[i]=h; lo[i]=l; }
}
__global__ void bias_int(const float* __restrict__ b, float* __restrict__ o){
    int i = threadIdx.x + blockIdx.x*256;       // i = dim*4+gate
    int gate = i & 3, dim = i >> 2;
    o[i] = b[gate*1024 + dim];
}

// ---------------- fused 3-term fp16 GEMM (+ optional LSTM-cell epilogue) ----------------
// mode 0: plain store   mode 1: permuted store (final linear)   mode 2: fused cell
__global__ void __launch_bounds__(512,1) gemm3h(
    const __half* __restrict__ A1h, const __half* __restrict__ A1l,
    const __half* __restrict__ B1h, const __half* __restrict__ B1l,
    const __half* __restrict__ A2h, const __half* __restrict__ A2l,
    const __half* __restrict__ B2h, const __half* __restrict__ B2l,
    const float* __restrict__ Cin, const float* __restrict__ bias1,
    const float* __restrict__ bias2,
    float* __restrict__ C,
    float* __restrict__ cstate, __half* __restrict__ houth, __half* __restrict__ houtl,
    int N, int K, int nseg, int mode)
{
    extern __shared__ char smc[];
    const int tid  = threadIdx.x;
    const int wid  = tid >> 5, lane = tid & 31;
    const int g    = lane >> 2, t = lane & 3;
    const int sub  = lane >> 3, rl = lane & 7;
    const int wM   = wid & 1;
    const int wN   = wid >> 1;
    const int m0   = blockIdx.y * TM;
    const int n0   = blockIdx.x * TN;

    const int S1 = K / BK;
    const int S  = S1 * nseg;

    float acc[4][4][4];
    #pragma unroll
    for (int i=0;i<4;i++) for (int j=0;j<4;j++) for (int q=0;q<4;q++) acc[i][j][q]=0.f;

    auto load_stage = [&](int s){
        const __half *Ah = A1h, *Al = A1l, *Bh = B1h, *Bl = B1l; int k0;
        if (s >= S1){ Ah=A2h; Al=A2l; Bh=B2h; Bl=B2l; k0 = (s - S1)*BK; } else k0 = s*BK;
        uint32_t st = s2u(smc + (s % NSTAGE) * STG_BYTES);
        {
            int row = tid >> 2, gran = tid & 3;
            uint32_t doff = (uint32_t)(row*64 + ((gran ^ (row & 3))<<4));
            size_t soff = (size_t)(m0+row)*K + k0 + gran*8;
            cp16(st + doff,            Ah + soff);
            cp16(st + A_BYTES + doff,  Al + soff);
        }
        #pragma unroll
        for (int j = 0; j < 2; j++){
            int e = tid + j*512;
            int row = e >> 2, gran = e & 3;
            uint32_t doff = (uint32_t)(row*64 + ((gran ^ (row & 3))<<4));
            size_t soff = (size_t)(n0+row)*K + k0 + gran*8;
            cp16(st + 2*A_BYTES + doff,            Bh + soff);
            cp16(st + 2*A_BYTES + B_BYTES + doff,  Bl + soff);
        }
        CP_COMMIT();
    };

    load_stage(0); load_stage(1);

    for (int s = 0; s < S; s++){
        if (s < S-1) asm volatile("cp.async.wait_group 1;" ::: "memory");
        else         asm volatile("cp.async.wait_group 0;" ::: "memory");
        __syncthreads();
        if (s + 2 < S) load_stage(s + 2);     // overlaps with MMAs below

        uint32_t sa = s2u(smc + (s % NSTAGE) * STG_BYTES);
        uint32_t sbB = sa + 2*A_BYTES;

        #pragma unroll
        for (int ks = 0; ks < 2; ks++){
            const int gran = 2*ks + (sub >> 1);
            uint32_t ah[4][4], al[4][4];
            #pragma unroll
            for (int mb = 0; mb < 4; mb++){
                int row = wM*64 + mb*16 + ((sub & 1)<<3) + rl;
                uint32_t off = (uint32_t)(row*64 + ((gran ^ (row & 3))<<4));
                ldsm4(ah[mb][0], ah[mb][1], ah[mb][2], ah[mb][3], sa + off);
                ldsm4(al[mb][0], al[mb][1], al[mb][2], al[mb][3], sa + A_BYTES + off);
            }
            #pragma unroll
            for (int np = 0; np < 2; np++){
                int row = wN*32 + np*16 + ((sub & 1)<<3) + rl;
                uint32_t off = (uint32_t)(row*64 + ((gran ^ (row & 3))<<4));
                uint32_t h0,h1,h2,h3, l0,l1,l2,l3;
                ldsm4(h0,h1,h2,h3, sbB + off);
                ldsm4(l0,l1,l2,l3, sbB + B_BYTES + off);
                uint32_t bh[2][2] = {{h0,h2},{h1,h3}};
                uint32_t bl[2][2] = {{l0,l2},{l1,l3}};
                #pragma unroll
                for (int mb = 0; mb < 4; mb++)
                    #pragma unroll
                    for (int j = 0; j < 2; j++){
                        float* a = acc[mb][np*2 + j];
                        mma16(a, ah[mb], bh[j]);
                        mma16(a, ah[mb], bl[j]);
                        mma16(a, al[mb], bh[j]);
                    }
            }
        }
        __syncthreads();
    }

    // ---- epilogue ----
    if (mode == 2){
        // fused LSTM cell: cols are gate-interleaved (n = 4*dim + gate)
        const int tq = t >> 1, todd = t & 1;
        #pragma unroll
        for (int mb = 0; mb < 4; mb++){
            int mrow = m0 + wM*64 + mb*16 + g;
            #pragma unroll
            for (int nb = 0; nb < 4; nb++){
                int n = n0 + wN*32 + nb*8 + 2*t;
                float v0 = acc[mb][nb][0], v1 = acc[mb][nb][1];
                float v2 = acc[mb][nb][2], v3 = acc[mb][nb][3];
                float b0 = bias1[n], b1 = bias1[n+1];
                if (bias2){ b0 += bias2[n]; b1 += bias2[n+1]; }
                v0 += b0; v1 += b1; v2 += b0; v3 += b1;
                if (Cin){
                    float2 ca = *(const float2*)(Cin + (size_t)mrow*N + n);
                    float2 cb = *(const float2*)(Cin + (size_t)(mrow+8)*N + n);
                    v0 += ca.x; v1 += ca.y; v2 += cb.x; v3 += cb.y;
                }
                float p0 = __shfl_xor_sync(0xffffffffu, v0, 1);
                float p1 = __shfl_xor_sync(0xffffffffu, v1, 1);
                float p2 = __shfl_xor_sync(0xffffffffu, v2, 1);
                float p3 = __shfl_xor_sync(0xffffffffu, v3, 1);
                float gi, gf, gg, go; int brow;
                if (!todd){ gi=v0; gf=v1; gg=p0; go=p1; brow = mrow; }
                else      { gi=p2; gf=p3; gg=v2; go=v3; brow = mrow+8; }
                int dim = ((n0 + wN*32 + nb*8) >> 2) + tq;
                int idx = brow*D_ + dim;
                float cn = sigf(gf)*cstate[idx] + sigf(gi)*tanhf(gg);
                cstate[idx] = cn;
                float hv = sigf(go)*tanhf(cn);
                __half hh_, hl_; hsplit(hv, hh_, hl_);
                houth[idx] = hh_; houtl[idx] = hl_;
            }
        }
    } else {
        #pragma unroll
        for (int mb = 0; mb < 4; mb++){
            #pragma unroll
            for (int half = 0; half < 2; half++){
                int m = m0 + wM*64 + mb*16 + g + half*8;
                size_t rowoff;
                if (mode == 1){ int tt = m >> 10, bb = m & 1023; rowoff = ((size_t)bb*BAR_ + tt)*(size_t)N; }
                else          { rowoff = (size_t)m*(size_t)N; }
                #pragma unroll
                for (int nb = 0; nb < 4; nb++){
                    int n = n0 + wN*32 + nb*8 + 2*t;
                    float v0 = acc[mb][nb][half*2 + 0];
                    float v1 = acc[mb][nb][half*2 + 1];
                    if (bias1){ v0 += bias1[n]; v1 += bias1[n+1]; }
                    if (Cin){
                        float2 cv = *(const float2*)(Cin + (size_t)m*(size_t)N + n);
                        v0 += cv.x; v1 += cv.y;
                    }
                    float2 o; o.x = v0; o.y = v1;
                    *(float2*)(C + rowoff + n) = o;
                }
            }
        }
    }
}

// ---------------- launcher ----------------
extern "C" void kernel_launch(void* const* d_in, const int* in_sizes, int n_in,
                              void* d_out, int out_size)
{
    const float* z     = (const float*)d_in[0];
    const float* gamma = (const float*)d_in[1];
    const float* beta  = (const float*)d_in[2];
    const float* W_ih0 = (const float*)d_in[3];
    const float* W_hh0 = (const float*)d_in[4];
    const float* b_ih0 = (const float*)d_in[5];
    const float* b_hh0 = (const float*)d_in[6];
    const float* W_ih1 = (const float*)d_in[7];
    const float* W_hh1 = (const float*)d_in[8];
    const float* b_ih1 = (const float*)d_in[9];
    const float* b_hh1 = (const float*)d_in[10];
    const float* W_lin = (const float*)d_in[11];
    const float* b_lin = (const float*)d_in[12];
    float* out = (float*)d_out;

    cudaFuncSetAttribute(gemm3h, cudaFuncAttributeMaxDynamicSharedMemorySize, SMEM_BYTES);

    float *x0,*c0,*c1,*bi0,*bh0,*bi1,*bh1;
    __half *znh,*znl,*hh,*hl;
    __half *h0h[2], *h0l[2];
    __half *wih0h,*wih0l,*whh0h,*whh0l,*wih1h,*wih1l,*whh1h,*whh1l,*wlinh,*wlinl;
    cudaGetSymbolAddress((void**)&x0,  g_x0);
    cudaGetSymbolAddress((void**)&c0,  g_c0);
    cudaGetSymbolAddress((void**)&c1,  g_c1);
    cudaGetSymbolAddress((void**)&bi0, g_bi0); cudaGetSymbolAddress((void**)&bh0, g_bh0);
    cudaGetSymbolAddress((void**)&bi1, g_bi1); cudaGetSymbolAddress((void**)&bh1, g_bh1);
    cudaGetSymbolAddress((void**)&znh, g_znh); cudaGetSymbolAddress((void**)&znl, g_znl);
    cudaGetSymbolAddress((void**)&hh,  g_histh); cudaGetSymbolAddress((void**)&hl, g_histl);
    {
        __half* p;
        cudaGetSymbolAddress((void**)&p, g_h0h); h0h[0]=p; h0h[1]=p + (size_t)B_*D_;
        cudaGetSymbolAddress((void**)&p, g_h0l); h0l[0]=p; h0l[1]=p + (size_t)B_*D_;
    }
    cudaGetSymbolAddress((void**)&wih0h, g_wih0h); cudaGetSymbolAddress((void**)&wih0l, g_wih0l);
    cudaGetSymbolAddress((void**)&whh0h, g_whh0h); cudaGetSymbolAddress((void**)&whh0l, g_whh0l);
    cudaGetSymbolAddress((void**)&wih1h, g_wih1h); cudaGetSymbolAddress((void**)&wih1l, g_wih1l);
    cudaGetSymbolAddress((void**)&whh1h, g_whh1h); cudaGetSymbolAddress((void**)&whh1l, g_whh1l);
    cudaGetSymbolAddress((void**)&wlinh, g_wlinh); cudaGetSymbolAddress((void**)&wlinl, g_wlinl);

    const int GD = G_*D_, DD = D_*D_;
    split_int<<<GD/256, 256>>>(W_ih0, wih0h, wih0l);
    split_int<<<GD/256, 256>>>(W_hh0, whh0h, whh0l);
    split_int<<<GD/256, 256>>>(W_ih1, wih1h, wih1l);
    split_int<<<GD/256, 256>>>(W_hh1, whh1h, whh1l);
    split_plain<<<DD/256, 256>>>(W_lin, wlinh, wlinl, DD);
    bias_int<<<G_/256, 256>>>(b_ih0, bi0);
    bias_int<<<G_/256, 256>>>(b_hh0, bh0);
    bias_int<<<G_/256, 256>>>(b_ih1, bi1);
    bias_int<<<G_/256, 256>>>(b_hh1, bh1);

    bn_reduce<<<D_, 256>>>(z);
    bn_apply<<<(B_*D_)/256, 256>>>(z, gamma, beta);

    // x0_proj (interleaved cols) = zn @ Wih0_int^T + bi0
    gemm3h<<<dim3(G_/TN, B_/TM), 512, SMEM_BYTES>>>(
        znh, znl, wih0h, wih0l, nullptr, nullptr, nullptr, nullptr,
        nullptr, bi0, nullptr, x0, nullptr, nullptr, nullptr, G_, D_, 1, 0);

    const size_t BD = (size_t)B_*D_;
    for (int t = 0; t < BAR_; t++){
        int p = t & 1;
        // fused: gates0 = x0 + h0 @ Whh0^T + bh0 ; cell -> h0 (other buffer), c0
        gemm3h<<<dim3(G_/TN, B_/TM), 512, SMEM_BYTES>>>(
            h0h[p], h0l[p], whh0h, whh0l, nullptr, nullptr, nullptr, nullptr,
            x0, bh0, nullptr, nullptr, c0, h0h[1-p], h0l[1-p], G_, D_, 1, 2);

        // fused: gates1 = h0 @ Wih1^T + h1prev @ Whh1^T + bi1 + bh1 ; cell -> hist[t], c1
        const __half* h1ph = (t == 0) ? znh : (hh + (size_t)(t-1)*BD);
        const __half* h1pl = (t == 0) ? znl : (hl + (size_t)(t-1)*BD);
        gemm3h<<<dim3(G_/TN, B_/TM), 512, SMEM_BYTES>>>(
            h0h[1-p], h0l[1-p], wih1h, wih1l, h1ph, h1pl, whh1h, whh1l,
            nullptr, bi1, bh1, nullptr, c1, hh + (size_t)t*BD, hl + (size_t)t*BD,
            G_, D_, 2, 2);
    }

    // out[b][t][:] = hist[t][b][:] @ W_lin^T + b_lin  (permuted store)
    gemm3h<<<dim3(D_/TN, (BAR_*B_)/TM), 512, SMEM_BYTES>>>(
        hh, hl, wlinh, wlinl, nullptr, nullptr, nullptr, nullptr,
        nullptr, b_lin, nullptr, out, nullptr, nullptr, nullptr, D_, D_, 1, 1);
}

// round 12
// speedup vs baseline: 1.1334x; 1.1334x over previous
#include <cuda_runtime.h>
#include <cuda_fp16.h>
#include <cstdint>

#define B_   1024
#define D_   1024
#define G_   4096
#define BAR_ 32
#define EPS_ 1e-5f

// GEMM tiling: CTA 128x256, BK=32, 512 threads (16 warps, each 64x32)
#define TM 128
#define TN 256
#define BK 32
#define NSTAGE 3
#define A_BYTES  (TM*BK*2)                // 8192 per array
#define B_BYTES  (TN*BK*2)                // 16384 per array
#define STG_BYTES (2*A_BYTES + 2*B_BYTES) // 49152
#define SMEM_BYTES (NSTAGE*STG_BYTES)     // 147456
#define GD (G_*D_)
#define DD (D_*D_)

// ---------------- device scratch ----------------
__device__ float g_sum[D_], g_sumsq[D_];
__device__ float g_x0[B_*G_];
__device__ float g_gates[B_*G_];
__device__ float g_c0[B_*D_], g_c1[B_*D_];
__device__ __align__(128) __half g_znh[B_*D_],  g_znl[B_*D_];
__device__ __align__(128) __half g_h0h[B_*D_],  g_h0l[B_*D_];
__device__ __align__(128) __half g_histh[(size_t)BAR_*B_*D_], g_histl[(size_t)BAR_*B_*D_];
__device__ __align__(128) __half g_wih0h[GD], g_wih0l[GD];
__device__ __align__(128) __half g_whh0h[GD], g_whh0l[GD];
__device__ __align__(128) __half g_wih1h[GD], g_wih1l[GD];
__device__ __align__(128) __half g_whh1h[GD], g_whh1l[GD];
__device__ __align__(128) __half g_wlinh[DD], g_wlinl[DD];

// ---------------- helpers ----------------
__device__ __forceinline__ uint32_t s2u(const void* p){
    uint32_t a;
    asm("{ .reg .u64 t; cvta.to.shared.u64 t, %1; cvt.u32.u64 %0, t; }" : "=r"(a) : "l"(p));
    return a;
}
__device__ __forceinline__ float sigf(float x){ return 1.f/(1.f+__expf(-x)); }

__device__ __forceinline__ void hsplit(float x, __half& hi, __half& lo){
    __half h = __float2half_rn(x);
    hi = h;
    lo = __float2half_rn(x - __half2float(h));
}

__device__ __forceinline__ void cp16(uint32_t dst, const void* src){
    asm volatile("cp.async.cg.shared.global [%0], [%1], 16;"
                 :: "r"(dst), "l"(__cvta_generic_to_global(src)));
}
#define CP_COMMIT() asm volatile("cp.async.commit_group;" ::: "memory")

__device__ __forceinline__ void mma16(float* c, const uint32_t* a, const uint32_t* b){
    asm volatile(
        "mma.sync.aligned.m16n8k16.row.col.f32.f16.f16.f32 "
        "{%0,%1,%2,%3}, {%4,%5,%6,%7}, {%8,%9}, {%0,%1,%2,%3};"
        : "+f"(c[0]), "+f"(c[1]), "+f"(c[2]), "+f"(c[3])
        : "r"(a[0]), "r"(a[1]), "r"(a[2]), "r"(a[3]), "r"(b[0]), "r"(b[1]));
}
__device__ __forceinline__ void ldsm4(uint32_t& r0, uint32_t& r1, uint32_t& r2,
                                      uint32_t& r3, uint32_t addr){
    asm volatile("ldmatrix.sync.aligned.m8n8.x4.shared.b16 {%0,%1,%2,%3}, [%4];"
                 : "=r"(r0), "=r"(r1), "=r"(r2), "=r"(r3) : "r"(addr));
}

// ---------------- combined weight split (one launch) ----------------
__global__ void split_all(const float* __restrict__ W_ih0, const float* __restrict__ W_hh0,
                          const float* __restrict__ W_ih1, const float* __restrict__ W_hh1,
                          const float* __restrict__ W_lin){
    int i = blockIdx.x*256 + threadIdx.x;
    const float* src; __half *hi, *lo; int off;
    if      (i <   GD){ src=W_ih0; hi=g_wih0h; lo=g_wih0l; off=i; }
    else if (i < 2*GD){ src=W_hh0; hi=g_whh0h; lo=g_whh0l; off=i-GD; }
    else if (i < 3*GD){ src=W_ih1; hi=g_wih1h; lo=g_wih1l; off=i-2*GD; }
    else if (i < 4*GD){ src=W_hh1; hi=g_whh1h; lo=g_whh1l; off=i-3*GD; }
    else if (i < 4*GD+DD){ src=W_lin; hi=g_wlinh; lo=g_wlinl; off=i-4*GD; }
    else return;
    __half h, l; hsplit(src[off], h, l);
    hi[off]=h; lo[off]=l;
}

// ---------------- BatchNorm ----------------
__global__ void bn_reduce(const float* __restrict__ z){
    int c = blockIdx.x, tid = threadIdx.x;
    float s = 0.f, s2 = 0.f;
    for (int r = tid; r < B_; r += 256){
        float v = z[(size_t)r*D_ + c]; s += v; s2 += v*v;
    }
    __shared__ float sh[256], sh2[256];
    sh[tid]=s; sh2[tid]=s2; __syncthreads();
    for (int o=128;o>0;o>>=1){
        if (tid<o){ sh[tid]+=sh[tid+o]; sh2[tid]+=sh2[tid+o]; }
        __syncthreads();
    }
    if (tid==0){ g_sum[c]=sh[0]; g_sumsq[c]=sh2[0]; }
}

__global__ void bn_apply(const float* __restrict__ z, const float* __restrict__ gamma,
                         const float* __restrict__ beta){
    int idx = blockIdx.x*256 + threadIdx.x;
    int d = idx & (D_-1);
    float mean = g_sum[d]*(1.f/B_);
    float var  = g_sumsq[d]*(1.f/B_) - mean*mean;
    float v = (z[idx]-mean)*rsqrtf(var+EPS_)*gamma[d] + beta[d];
    __half h, l; hsplit(v, h, l);
    g_znh[idx]=h; g_znl[idx]=l;
    g_h0h[idx]=h; g_h0l[idx]=l;
    g_c0[idx]=v;  g_c1[idx]=v;
}

// ---------------- LSTM cell (vectorized x4) ----------------
__global__ void lstm_cell(const float* __restrict__ gates, float* __restrict__ c,
                          __half* __restrict__ hh, __half* __restrict__ hl){
    int i = blockIdx.x*256 + threadIdx.x;      // over B_*D_/4
    int b = i >> 8, d4 = (i & 255) << 2;       // D_/4 = 256 vectors per row
    const float* gr = gates + (size_t)b*G_;
    float4 gi = *(const float4*)(gr + d4);
    float4 gf = *(const float4*)(gr + D_ + d4);
    float4 gg = *(const float4*)(gr + 2*D_ + d4);
    float4 go = *(const float4*)(gr + 3*D_ + d4);
    int idx = b*D_ + d4;
    float4 cv = *(float4*)(c + idx);
    float cn0 = sigf(gf.x)*cv.x + sigf(gi.x)*tanhf(gg.x);
    float cn1 = sigf(gf.y)*cv.y + sigf(gi.y)*tanhf(gg.y);
    float cn2 = sigf(gf.z)*cv.z + sigf(gi.z)*tanhf(gg.z);
    float cn3 = sigf(gf.w)*cv.w + sigf(gi.w)*tanhf(gg.w);
    float4 co; co.x=cn0; co.y=cn1; co.z=cn2; co.w=cn3;
    *(float4*)(c + idx) = co;
    float h0 = sigf(go.x)*tanhf(cn0);
    float h1 = sigf(go.y)*tanhf(cn1);
    float h2 = sigf(go.z)*tanhf(cn2);
    float h3 = sigf(go.w)*tanhf(cn3);
    __half a0,b0,a1,b1,a2,b2,a3,b3;
    hsplit(h0,a0,b0); hsplit(h1,a1,b1); hsplit(h2,a2,b2); hsplit(h3,a3,b3);
    __half2 hhv0 = __halves2half2(a0,a1), hhv1 = __halves2half2(a2,a3);
    __half2 hlv0 = __halves2half2(b0,b1), hlv1 = __halves2half2(b2,b3);
    uint2 uh; uh.x = *(uint32_t*)&hhv0; uh.y = *(uint32_t*)&hhv1;
    uint2 ul; ul.x = *(uint32_t*)&hlv0; ul.y = *(uint32_t*)&hlv1;
    *(uint2*)(hh + idx) = uh;
    *(uint2*)(hl + idx) = ul;
}

// ---------------- 3-term fp16 mma.sync GEMM (NT, K-fused) ----------------
// C = [Cin] + bias1 [+bias2] + sum_seg (Ah+Al)(Bh+Bl)^T  (hh+hl+lh terms)
__global__ void __launch_bounds__(512,1) gemm3h(
    const __half* __restrict__ A1h, const __half* __restrict__ A1l,
    const __half* __restrict__ B1h, const __half* __restrict__ B1l,
    const __half* __restrict__ A2h, const __half* __restrict__ A2l,
    const __half* __restrict__ B2h, const __half* __restrict__ B2l,
    const float* __restrict__ Cin, const float* __restrict__ bias1,
    const float* __restrict__ bias2,
    float* __restrict__ C, int N, int K, int nseg, int permute)
{
    extern __shared__ char smc[];
    const int tid  = threadIdx.x;
    const int wid  = tid >> 5, lane = tid & 31;
    const int g    = lane >> 2, t = lane & 3;
    const int sub  = lane >> 3, rl = lane & 7;
    const int wM   = wid & 1;
    const int wN   = wid >> 1;
    const int m0   = blockIdx.y * TM;
    const int n0   = blockIdx.x * TN;

    const int S1 = K / BK;
    const int S  = S1 * nseg;

    float acc[4][4][4];
    #pragma unroll
    for (int i=0;i<4;i++) for (int j=0;j<4;j++) for (int q=0;q<4;q++) acc[i][j][q]=0.f;

    auto load_stage = [&](int s){
        const __half *Ah = A1h, *Al = A1l, *Bh = B1h, *Bl = B1l; int k0;
        if (s >= S1){ Ah=A2h; Al=A2l; Bh=B2h; Bl=B2l; k0 = (s - S1)*BK; } else k0 = s*BK;
        uint32_t st = s2u(smc + (s % NSTAGE) * STG_BYTES);
        {
            int row = tid >> 2, gran = tid & 3;
            uint32_t doff = (uint32_t)(row*64 + ((gran ^ (row & 3))<<4));
            size_t soff = (size_t)(m0+row)*K + k0 + gran*8;
            cp16(st + doff,            Ah + soff);
            cp16(st + A_BYTES + doff,  Al + soff);
        }
        #pragma unroll
        for (int j = 0; j < 2; j++){
            int e = tid + j*512;
            int row = e >> 2, gran = e & 3;
            uint32_t doff = (uint32_t)(row*64 + ((gran ^ (row & 3))<<4));
            size_t soff = (size_t)(n0+row)*K + k0 + gran*8;
            cp16(st + 2*A_BYTES + doff,            Bh + soff);
            cp16(st + 2*A_BYTES + B_BYTES + doff,  Bl + soff);
        }
        CP_COMMIT();
    };

    load_stage(0); load_stage(1);

    for (int s = 0; s < S; s++){
        if (s < S-1) asm volatile("cp.async.wait_group 1;" ::: "memory");
        else         asm volatile("cp.async.wait_group 0;" ::: "memory");
        __syncthreads();                       // single barrier per stage
        if (s + 2 < S) load_stage(s + 2);      // overlaps with MMAs below

        uint32_t sa = s2u(smc + (s % NSTAGE) * STG_BYTES);
        uint32_t sbB = sa + 2*A_BYTES;

        #pragma unroll
        for (int ks = 0; ks < 2; ks++){
            const int gran = 2*ks + (sub >> 1);
            uint32_t ah[4][4], al[4][4];
            #pragma unroll
            for (int mb = 0; mb < 4; mb++){
                int row = wM*64 + mb*16 + ((sub & 1)<<3) + rl;
                uint32_t off = (uint32_t)(row*64 + ((gran ^ (row & 3))<<4));
                ldsm4(ah[mb][0], ah[mb][1], ah[mb][2], ah[mb][3], sa + off);
                ldsm4(al[mb][0], al[mb][1], al[mb][2], al[mb][3], sa + A_BYTES + off);
            }
            #pragma unroll
            for (int np = 0; np < 2; np++){
                int row = wN*32 + np*16 + ((sub & 1)<<3) + rl;
                uint32_t off = (uint32_t)(row*64 + ((gran ^ (row & 3))<<4));
                uint32_t h0,h1,h2,h3, l0,l1,l2,l3;
                ldsm4(h0,h1,h2,h3, sbB + off);
                ldsm4(l0,l1,l2,l3, sbB + B_BYTES + off);
                uint32_t bh[2][2] = {{h0,h2},{h1,h3}};
                uint32_t bl[2][2] = {{l0,l2},{l1,l3}};
                #pragma unroll
                for (int mb = 0; mb < 4; mb++)
                    #pragma unroll
                    for (int j = 0; j < 2; j++){
                        float* a = acc[mb][np*2 + j];
                        mma16(a, ah[mb], bh[j]);
                        mma16(a, ah[mb], bl[j]);
                        mma16(a, al[mb], bh[j]);
                    }
            }
        }
    }

    // ---- epilogue ----
    #pragma unroll
    for (int mb = 0; mb < 4; mb++){
        #pragma unroll
        for (int half = 0; half < 2; half++){
            int m = m0 + wM*64 + mb*16 + g + half*8;
            size_t rowoff;
            if (permute){ int tt = m >> 10, bb = m & 1023; rowoff = ((size_t)bb*BAR_ + tt)*(size_t)N; }
            else        { rowoff = (size_t)m*(size_t)N; }
            #pragma unroll
            for (int nb = 0; nb < 4; nb++){
                int n = n0 + wN*32 + nb*8 + 2*t;
                float v0 = acc[mb][nb][half*2 + 0];
                float v1 = acc[mb][nb][half*2 + 1];
                if (bias1){ v0 += bias1[n]; v1 += bias1[n+1]; }
                if (bias2){ v0 += bias2[n]; v1 += bias2[n+1]; }
                if (Cin){
                    float2 cv = *(const float2*)(Cin + (size_t)m*(size_t)N + n);
                    v0 += cv.x; v1 += cv.y;
                }
                float2 o; o.x = v0; o.y = v1;
                *(float2*)(C + rowoff + n) = o;
            }
        }
    }
}

// ---------------- launcher ----------------
extern "C" void kernel_launch(void* const* d_in, const int* in_sizes, int n_in,
                              void* d_out, int out_size)
{
    const float* z     = (const float*)d_in[0];
    const float* gamma = (const float*)d_in[1];
    const float* beta  = (const float*)d_in[2];
    const float* W_ih0 = (const float*)d_in[3];
    const float* W_hh0 = (const float*)d_in[4];
    const float* b_ih0 = (const float*)d_in[5];
    const float* b_hh0 = (const float*)d_in[6];
    const float* W_ih1 = (const float*)d_in[7];
    const float* W_hh1 = (const float*)d_in[8];
    const float* b_ih1 = (const float*)d_in[9];
    const float* b_hh1 = (const float*)d_in[10];
    const float* W_lin = (const float*)d_in[11];
    const float* b_lin = (const float*)d_in[12];
    float* out = (float*)d_out;

    cudaFuncSetAttribute(gemm3h, cudaFuncAttributeMaxDynamicSharedMemorySize, SMEM_BYTES);

    float *x0,*gates,*c0,*c1;
    __half *znh,*znl,*h0h,*h0l,*hh,*hl;
    __half *wih0h,*wih0l,*whh0h,*whh0l,*wih1h,*wih1l,*whh1h,*whh1l,*wlinh,*wlinl;
    cudaGetSymbolAddress((void**)&x0,    g_x0);
    cudaGetSymbolAddress((void**)&gates, g_gates);
    cudaGetSymbolAddress((void**)&c0,    g_c0);
    cudaGetSymbolAddress((void**)&c1,    g_c1);
    cudaGetSymbolAddress((void**)&znh,   g_znh);   cudaGetSymbolAddress((void**)&znl, g_znl);
    cudaGetSymbolAddress((void**)&h0h,   g_h0h);   cudaGetSymbolAddress((void**)&h0l, g_h0l);
    cudaGetSymbolAddress((void**)&hh,    g_histh); cudaGetSymbolAddress((void**)&hl,  g_histl);
    cudaGetSymbolAddress((void**)&wih0h, g_wih0h); cudaGetSymbolAddress((void**)&wih0l, g_wih0l);
    cudaGetSymbolAddress((void**)&whh0h, g_whh0h); cudaGetSymbolAddress((void**)&whh0l, g_whh0l);
    cudaGetSymbolAddress((void**)&wih1h, g_wih1h); cudaGetSymbolAddress((void**)&wih1l, g_wih1l);
    cudaGetSymbolAddress((void**)&whh1h, g_whh1h); cudaGetSymbolAddress((void**)&whh1l, g_whh1l);
    cudaGetSymbolAddress((void**)&wlinh, g_wlinh); cudaGetSymbolAddress((void**)&wlinl, g_wlinl);

    split_all<<<(4*GD+DD)/256, 256>>>(W_ih0, W_hh0, W_ih1, W_hh1, W_lin);
    bn_reduce<<<D_, 256>>>(z);
    bn_apply<<<(B_*D_)/256, 256>>>(z, gamma, beta);

    // x0_proj = zn @ W_ih0^T + b_ih0
    gemm3h<<<dim3(G_/TN, B_/TM), 512, SMEM_BYTES>>>(
        znh, znl, wih0h, wih0l, nullptr, nullptr, nullptr, nullptr,
        nullptr, b_ih0, nullptr, x0, G_, D_, 1, 0);

    const size_t BD = (size_t)B_*D_;
    for (int t = 0; t < BAR_; t++){
        // gates = x0 + h0 @ W_hh0^T + b_hh0
        gemm3h<<<dim3(G_/TN, B_/TM), 512, SMEM_BYTES>>>(
            h0h, h0l, whh0h, whh0l, nullptr, nullptr, nullptr, nullptr,
            x0, b_hh0, nullptr, gates, G_, D_, 1, 0);
        lstm_cell<<<(B_*D_)/1024, 256>>>(gates, c0, h0h, h0l);

        // gates = h0 @ W_ih1^T + h1prev @ W_hh1^T + b_ih1 + b_hh1 (fused K)
        const __half* h1ph = (t == 0) ? znh : (hh + (size_t)(t-1)*BD);
        const __half* h1pl = (t == 0) ? znl : (hl + (size_t)(t-1)*BD);
        gemm3h<<<dim3(G_/TN, B_/TM), 512, SMEM_BYTES>>>(
            h0h, h0l, wih1h, wih1l, h1ph, h1pl, whh1h, whh1l,
            nullptr, b_ih1, b_hh1, gates, G_, D_, 2, 0);
        lstm_cell<<<(B_*D_)/1024, 256>>>(gates, c1, hh + (size_t)t*BD, hl + (size_t)t*BD);
    }

    // out[b][t][:] = hist[t][b][:] @ W_lin^T + b_lin  (permuted store)
    gemm3h<<<dim3(D_/TN, (BAR_*B_)/TM), 512, SMEM_BYTES>>>(
        hh, hl, wlinh, wlinl, nullptr, nullptr, nullptr, nullptr,
        nullptr, b_lin, nullptr, out, D_, D_, 1, 1);
}